// round 15
// baseline (speedup 1.0000x reference)
#include <cuda_runtime.h>
#include <cuda_bf16.h>
#include <cuda_fp16.h>
#include <cstdint>

// ---------------------------------------------------------------------------
// RegressorHybrid on GB300 via mma.sync (HMMA fallback; tcgen05 not available
// at the harness's compute_103 PTX stage).
//
//   Precompute: P_src[n] = x_src[n] @ W1[0:64]  + bias1   (128 outs: e|w heads)
//               P_dst[n] = x_dst[n] @ W1[64:128]   (3-pass bf16; P stored FP16)
//   Main:       one HEAD per warp, 32 edges (two m16 tiles) per iteration so
//               each weight ldmatrix feeds 4 MMAs. act1 = lrelu(Ps+Pd)
//               computed entirely in HALF2 (HADD2+HMUL2+HMAX2, 3 instrs/pair)
//               straight into fp16 A fragments. L2/L3 single-pass fp16 mma;
//               448 threads (146-reg ceiling). L4 scalar dot in fp32.
// ---------------------------------------------------------------------------

#define NE      2000000
#define NNODES  50000
#define NPAD    50048

__device__ __align__(256) __half g_Psrc[(size_t)NPAD * 128];
__device__ __align__(256) __half g_Pdst[(size_t)NPAD * 128];
__device__ int g_flag;   // 1 => edge_label_index is int64

// W2 k-row placement: logical k (0..63) -> physical fragment row, such that
// lane tq's ONE uint4 (8 contiguous fp16 features, logical k = 32b+8tq+j)
// fills its A-fragment slots of kf-groups {2b, 2b+1}.
static __device__ __forceinline__ int kplace(int k) {
    int b = k >> 5, tq = (k >> 3) & 3, j = k & 7;
    int kf = 2 * b + (j >> 2);
    int kp = 2 * tq + (j & 1) + ((j >> 1) & 1) * 8;
    return kf * 16 + kp;
}

// ------------------------------- asm helpers -------------------------------
static __device__ __forceinline__ void ldsm4(uint32_t* r, uint32_t a) {
    asm volatile("ldmatrix.sync.aligned.m8n8.x4.shared.b16 {%0,%1,%2,%3},[%4];"
                 : "=r"(r[0]), "=r"(r[1]), "=r"(r[2]), "=r"(r[3]) : "r"(a));
}
static __device__ __forceinline__ void ldsm4t(uint32_t* r, uint32_t a) {
    asm volatile("ldmatrix.sync.aligned.m8n8.x4.trans.shared.b16 {%0,%1,%2,%3},[%4];"
                 : "=r"(r[0]), "=r"(r[1]), "=r"(r[2]), "=r"(r[3]) : "r"(a));
}
// bf16 mma (precompute kernel)
static __device__ __forceinline__ void mma16816(float* d, const uint32_t* a,
                                                uint32_t b0, uint32_t b1) {
    asm volatile("mma.sync.aligned.m16n8k16.row.col.f32.bf16.bf16.f32 "
                 "{%0,%1,%2,%3},{%4,%5,%6,%7},{%8,%9},{%0,%1,%2,%3};"
                 : "+f"(d[0]), "+f"(d[1]), "+f"(d[2]), "+f"(d[3])
                 : "r"(a[0]), "r"(a[1]), "r"(a[2]), "r"(a[3]), "r"(b0), "r"(b1));
}
// fp16 mma (main kernel)
static __device__ __forceinline__ void mmah(float* d, const uint32_t* a,
                                            uint32_t b0, uint32_t b1) {
    asm volatile("mma.sync.aligned.m16n8k16.row.col.f32.f16.f16.f32 "
                 "{%0,%1,%2,%3},{%4,%5,%6,%7},{%8,%9},{%0,%1,%2,%3};"
                 : "+f"(d[0]), "+f"(d[1]), "+f"(d[2]), "+f"(d[3])
                 : "r"(a[0]), "r"(a[1]), "r"(a[2]), "r"(a[3]), "r"(b0), "r"(b1));
}
// pack two f32 -> bf16x2, x0 in LOW half
static __device__ __forceinline__ uint32_t pack2(float x0, float x1) {
    uint32_t r;
    asm("cvt.rn.bf16x2.f32 %0,%1,%2;" : "=r"(r) : "f"(x1), "f"(x0));
    return r;
}
// pack two f32 -> f16x2, x0 in LOW half
static __device__ __forceinline__ uint32_t pack2h(float x0, float x1) {
    uint32_t r;
    asm("cvt.rn.f16x2.f32 %0,%1,%2;" : "=r"(r) : "f"(x1), "f"(x0));
    return r;
}
static __device__ __forceinline__ float lrelu(float v) {
    return fmaxf(v, 0.01f * v);          // 2 ops: FMUL + FMNMX
}
// half2 leaky-relu on a packed f16x2 word: max(v, 0.01*v)
static __device__ __forceinline__ uint32_t lrelu_h2(uint32_t w, __half2 c) {
    __half2 v = *reinterpret_cast<__half2*>(&w);
    __half2 r = __hmax2(v, __hmul2(v, c));
    return *reinterpret_cast<uint32_t*>(&r);
}
// bf16 hi/lo split (precompute)
static __device__ __forceinline__ void split_pair(float v0, float v1,
                                                  uint32_t& hw, uint32_t& lw) {
    hw = pack2(v0, v1);
    float h0 = __uint_as_float(hw << 16);
    float h1 = __uint_as_float(hw & 0xFFFF0000u);
    lw = pack2(v0 - h0, v1 - h1);
}
static __device__ __forceinline__ void splitw(float v, __nv_bfloat16& h, __nv_bfloat16& l) {
    h = __float2bfloat16(v);
    l = __float2bfloat16(v - __bfloat162float(h));
}

// ---------------------------- precompute kernel ----------------------------
// blockIdx.y: 0 -> P_src (W1 rows 0..63, +bias), 1 -> P_dst (rows 64..127)
// block (0,0) additionally runs the edge-index dtype detection -> g_flag.
#define P_BW1H 0
#define P_BW1L 17408
#define P_B1   34816
#define P_A    35840
#define P_AW   4608
#define P_SMEM (P_A + 16 * P_AW)      // 109568

__global__ void __launch_bounds__(512, 1) precompute_kernel(
    const float* __restrict__ xs, const float* __restrict__ xd,
    const float* __restrict__ ew1, const float* __restrict__ eb1,
    const float* __restrict__ ww1, const float* __restrict__ wb1,
    const int* __restrict__ eidx_i32)
{
    extern __shared__ char sm[];
    __shared__ int found;
    uint32_t su = (uint32_t)__cvta_generic_to_shared(sm);
    const int tid = threadIdx.x, lane = tid & 31, wid = tid >> 5;
    const int table = blockIdx.y;
    const float* x = table ? xd : xs;
    __half* P = table ? g_Pdst : g_Psrc;

    // ---- edge-index dtype detection (block (0,0) only) ----
    if (blockIdx.x == 0 && table == 0) {
        if (tid == 0) found = 0;
        __syncthreads();
        int acc = 0;
#pragma unroll 4
        for (int i = 0; i < 32; i++) {
            int j = tid * 32 + i;          // j < 16384, safe for both dtypes
            acc |= eidx_i32[2 * j + 1];
        }
        if (acc) atomicOr(&found, 1);
        __syncthreads();
        if (tid == 0) g_flag = found ? 0 : 1;
    }

    // B = W1 rows [table*64, +64), concat e|w heads, K-major [k][n] pad 136
    for (int i = tid; i < 64 * 128; i += 512) {
        int k = i >> 7, n = i & 127;
        int kg = k + table * 64;
        float v = (n < 64) ? ew1[kg * 64 + n] : ww1[kg * 64 + (n - 64)];
        __nv_bfloat16 h, l; splitw(v, h, l);
        *(__nv_bfloat16*)(sm + P_BW1H + (k * 136 + n) * 2) = h;
        *(__nv_bfloat16*)(sm + P_BW1L + (k * 136 + n) * 2) = l;
    }
    if (tid < 128) ((float*)(sm + P_B1))[tid] = (tid < 64) ? eb1[tid] : wb1[tid - 64];
    __syncthreads();

    const int nbase = (blockIdx.x * 16 + wid) * 16;

    // gather 16 node rows into per-warp A tile (16 x 64, pad 72), hi/lo split
    {
        int r = lane >> 1, ch = lane & 1;
        int node = nbase + r; if (node >= NNODES) node = NNODES - 1;
        const float* xr = x + (size_t)node * 64 + ch * 32;
        char* ab = sm + P_A + wid * P_AW + r * 144 + ch * 64;
#pragma unroll
        for (int j = 0; j < 4; j++) {
            float4 a = *(const float4*)(xr + j * 8);
            float4 b = *(const float4*)(xr + j * 8 + 4);
            uint32_t h0, l0, h1, l1, h2, l2, h3, l3;
            split_pair(a.x, a.y, h0, l0); split_pair(a.z, a.w, h1, l1);
            split_pair(b.x, b.y, h2, l2); split_pair(b.z, b.w, h3, l3);
            *(uint4*)(ab + j * 16)        = make_uint4(h0, h1, h2, h3);
            *(uint4*)(ab + 2304 + j * 16) = make_uint4(l0, l1, l2, l3);
        }
    }
    __syncwarp();

    uint32_t Ah[16], Al[16];
    uint32_t aaddr = su + P_A + wid * P_AW + (lane & 15) * 144 + (lane >> 4) * 16;
#pragma unroll
    for (int kf = 0; kf < 4; kf++) {
        ldsm4(Ah + kf * 4, aaddr + kf * 32);
        ldsm4(Al + kf * 4, aaddr + 2304 + kf * 32);
    }

    float acc[64];
#pragma unroll
    for (int i = 0; i < 64; i++) acc[i] = 0.f;

    uint32_t bcom = su + ((lane & 15) * 136 + (lane >> 4) * 8) * 2;
#pragma unroll
    for (int kf = 0; kf < 4; kf++) {
#pragma unroll
        for (int p = 0; p < 8; p++) {
            uint32_t bh[4]; ldsm4t(bh, bcom + P_BW1H + (kf * 16 * 136 + p * 16) * 2);
            mma16816(acc + (2 * p) * 4,     Ah + kf * 4, bh[0], bh[1]);
            mma16816(acc + (2 * p + 1) * 4, Ah + kf * 4, bh[2], bh[3]);
            mma16816(acc + (2 * p) * 4,     Al + kf * 4, bh[0], bh[1]);
            mma16816(acc + (2 * p + 1) * 4, Al + kf * 4, bh[2], bh[3]);
            uint32_t bl[4]; ldsm4t(bl, bcom + P_BW1L + (kf * 16 * 136 + p * 16) * 2);
            mma16816(acc + (2 * p) * 4,     Ah + kf * 4, bl[0], bl[1]);
            mma16816(acc + (2 * p + 1) * 4, Ah + kf * 4, bl[2], bl[3]);
        }
    }

    const float* b1s = (const float*)(sm + P_B1);
    int r0 = nbase + (lane >> 2), r1 = r0 + 8;
#pragma unroll
    for (int nf = 0; nf < 16; nf++) {
        int n0 = nf * 8 + (lane & 3) * 2;
        float a0 = 0.f, a1 = 0.f;
        if (table == 0) { a0 = b1s[n0]; a1 = b1s[n0 + 1]; }
        if (r0 < NNODES)
            *(uint32_t*)(P + (size_t)r0 * 128 + n0) = pack2h(acc[nf * 4 + 0] + a0, acc[nf * 4 + 1] + a1);
        if (r1 < NNODES)
            *(uint32_t*)(P + (size_t)r1 * 128 + n0) = pack2h(acc[nf * 4 + 2] + a0, acc[nf * 4 + 3] + a1);
    }
}

// ------------------------------- main kernel -------------------------------
// fp16 weight tables: W2 [h][64][72] (kplace'd rows), W3 [h][64][40]
#define M_W2  0
#define M_W3  18432
#define M_B2  28672
#define M_B3  29184
#define M_W4  29440
#define M_B4  29696
#define M_SMEM 30720

#define THREADS 448
#define HWARPS  7    // warps per head per CTA (14 warps total)

__global__ void __launch_bounds__(THREADS, 1) main_kernel(
    const void* __restrict__ eidx_raw,
    const float* __restrict__ ew2, const float* __restrict__ eb2,
    const float* __restrict__ ww2, const float* __restrict__ wb2,
    const float* __restrict__ ew3, const float* __restrict__ eb3,
    const float* __restrict__ ww3, const float* __restrict__ wb3,
    const float* __restrict__ ew4, const float* __restrict__ eb4,
    const float* __restrict__ ww4, const float* __restrict__ wb4,
    float* __restrict__ out)
{
    extern __shared__ char sm[];
    uint32_t su = (uint32_t)__cvta_generic_to_shared(sm);
    const int tid = threadIdx.x, lane = tid & 31, wid = tid >> 5;

    // weights (fp16): W2 rows at kplace(k) (gather-matched), W3 identity
    for (int i = tid; i < 2 * 64 * 64; i += THREADS) {
        int h = i >> 12, r = i & 4095, k = r >> 6, n = r & 63;
        float v = h ? ww2[k * 64 + n] : ew2[k * 64 + n];
        *(__half*)(sm + M_W2 + (h * 64 * 72 + kplace(k) * 72 + n) * 2) = __float2half(v);
    }
    for (int i = tid; i < 2 * 64 * 32; i += THREADS) {
        int h = i >> 11, r = i & 2047, k = r >> 5, n = r & 31;
        float v = h ? ww3[k * 32 + n] : ew3[k * 32 + n];
        *(__half*)(sm + M_W3 + (h * 64 * 40 + k * 40 + n) * 2) = __float2half(v);
    }
    if (tid < 128) ((float*)(sm + M_B2))[tid] = (tid < 64) ? eb2[tid] : wb2[tid - 64];
    else if (tid < 192) { int c = tid - 128; ((float*)(sm + M_B3))[c] = (c < 32) ? eb3[c] : wb3[c - 32]; }
    else if (tid < 256) { int c = tid - 192; ((float*)(sm + M_W4))[c] = (c < 32) ? ew4[c] : ww4[c - 32]; }
    if (tid == 256) { ((float*)(sm + M_B4))[0] = eb4[0]; ((float*)(sm + M_B4))[1] = wb4[0]; }
    __syncthreads();

    const int idx64 = g_flag;
    const long long* e64 = (const long long*)eidx_raw;
    const int* e32 = (const int*)eidx_raw;
    const float* b2s = (const float*)(sm + M_B2);
    const float* b3s = (const float*)(sm + M_B3);
    const float* w4s = (const float*)(sm + M_W4);
    const float* b4s = (const float*)(sm + M_B4);

    const __half2 c001 = __float2half2_rn(0.01f);

    const int h = wid & 1;                       // this warp's head
    const int hw = wid >> 1;                     // warp index within head: 0..6
    const uint32_t b2com = su + M_W2 + ((lane & 15) * 72 + (lane >> 4) * 8) * 2 + h * 9216;
    const uint32_t b3com = su + M_W3 + ((lane & 15) * 40 + (lane >> 4) * 8) * 2 + h * 5120;

    const int ngroups = NE / 32;                 // 62500 groups of 32 edges
    const int gstride = gridDim.x * HWARPS;
    const int rq = lane >> 2;                    // row 0..7 within m8
    const int cq = (lane & 3) * 2;               // col pair base within 8 (N dims)
    const int tq8 = (lane & 3) * 8;              // 8-feature base within 32-block

#define LDE(i) (idx64 ? (int)__ldg(e64 + (i)) : __ldg(e32 + (i)))

    int g = blockIdx.x * HWARPS + hw;
    int s0 = 0, s1 = 0, s2 = 0, s3 = 0, d0 = 0, d1 = 0, d2 = 0, d3 = 0;
    if (g < ngroups) {
        int r0 = g * 32 + rq;
        s0 = LDE(r0);      s1 = LDE(r0 + 8);      s2 = LDE(r0 + 16);      s3 = LDE(r0 + 24);
        d0 = LDE(NE + r0); d1 = LDE(NE + r0 + 8); d2 = LDE(NE + r0 + 16); d3 = LDE(NE + r0 + 24);
    }

    const size_t hco = (size_t)(h * 64 + tq8);

    for (; g < ngroups; ) {
        const int e0 = g * 32;
        const __half* ps0 = g_Psrc + (size_t)s0 * 128 + hco;
        const __half* pd0 = g_Pdst + (size_t)d0 * 128 + hco;
        const __half* ps1 = g_Psrc + (size_t)s1 * 128 + hco;
        const __half* pd1 = g_Pdst + (size_t)d1 * 128 + hco;
        const __half* ps2 = g_Psrc + (size_t)s2 * 128 + hco;
        const __half* pd2 = g_Pdst + (size_t)d2 * 128 + hco;
        const __half* ps3 = g_Psrc + (size_t)s3 * 128 + hco;
        const __half* pd3 = g_Pdst + (size_t)d3 * 128 + hco;

        // prefetch next iteration's indices (hides one L2 latency level)
        const int gn = g + gstride;
        if (gn < ngroups) {
            int r0 = gn * 32 + rq;
            s0 = LDE(r0);      s1 = LDE(r0 + 8);      s2 = LDE(r0 + 16);      s3 = LDE(r0 + 24);
            d0 = LDE(NE + r0); d1 = LDE(NE + r0 + 8); d2 = LDE(NE + r0 + 16); d3 = LDE(NE + r0 + 24);
        }

        // ---- gather act1 into fp16 A frags: 16 LDG.128, half2 math ----
        uint32_t Ah[32];
#define GATH(sa, da, idx) do { \
    __half2 _v = __hadd2(*(const __half2*)&(sa), *(const __half2*)&(da)); \
    __half2 _r = __hmax2(_v, __hmul2(_v, c001)); \
    Ah[idx] = *(uint32_t*)&_r; \
} while (0)
#pragma unroll
        for (int b = 0; b < 2; b++) {
            int co = b * 32;
            uint4 us0 = __ldg((const uint4*)(ps0 + co));
            uint4 ud0 = __ldg((const uint4*)(pd0 + co));
            uint4 us1 = __ldg((const uint4*)(ps1 + co));
            uint4 ud1 = __ldg((const uint4*)(pd1 + co));
            uint4 us2 = __ldg((const uint4*)(ps2 + co));
            uint4 ud2 = __ldg((const uint4*)(pd2 + co));
            uint4 us3 = __ldg((const uint4*)(ps3 + co));
            uint4 ud3 = __ldg((const uint4*)(pd3 + co));
            GATH(us0.x, ud0.x, 8 * b + 0);
            GATH(us0.y, ud0.y, 8 * b + 2);
            GATH(us0.z, ud0.z, 8 * b + 4);
            GATH(us0.w, ud0.w, 8 * b + 6);
            GATH(us1.x, ud1.x, 8 * b + 1);
            GATH(us1.y, ud1.y, 8 * b + 3);
            GATH(us1.z, ud1.z, 8 * b + 5);
            GATH(us1.w, ud1.w, 8 * b + 7);
            GATH(us2.x, ud2.x, 16 + 8 * b + 0);
            GATH(us2.y, ud2.y, 16 + 8 * b + 2);
            GATH(us2.z, ud2.z, 16 + 8 * b + 4);
            GATH(us2.w, ud2.w, 16 + 8 * b + 6);
            GATH(us3.x, ud3.x, 16 + 8 * b + 1);
            GATH(us3.y, ud3.y, 16 + 8 * b + 3);
            GATH(us3.z, ud3.z, 16 + 8 * b + 5);
            GATH(us3.w, ud3.w, 16 + 8 * b + 7);
        }
#undef GATH

        // ---- L2: M32 N64 K64, acc init = bias2, single fp16 pass ----
        float acc[64];
#pragma unroll
        for (int nf = 0; nf < 8; nf++) {
            int n0 = h * 64 + nf * 8 + cq;
            float2 bb = *(const float2*)(b2s + n0);
            acc[nf * 4 + 0] = bb.x; acc[nf * 4 + 1] = bb.y;
            acc[nf * 4 + 2] = bb.x; acc[nf * 4 + 3] = bb.y;
            acc[32 + nf * 4 + 0] = bb.x; acc[32 + nf * 4 + 1] = bb.y;
            acc[32 + nf * 4 + 2] = bb.x; acc[32 + nf * 4 + 3] = bb.y;
        }
#pragma unroll
        for (int kf = 0; kf < 4; kf++) {
#pragma unroll
            for (int p = 0; p < 4; p++) {
                uint32_t bh[4];
                ldsm4t(bh, b2com + (kf * 16 * 72 + p * 16) * 2);
#pragma unroll
                for (int m = 0; m < 2; m++) {
                    mmah(acc + m * 32 + (2 * p) * 4,     Ah + m * 16 + kf * 4, bh[0], bh[1]);
                    mmah(acc + m * 32 + (2 * p + 1) * 4, Ah + m * 16 + kf * 4, bh[2], bh[3]);
                }
            }
        }

        // ---- epilogue2: pack fp16 then half2 lrelu -> A3 frags (regs) ----
        uint32_t A3h[32];
#pragma unroll
        for (int m = 0; m < 2; m++) {
#pragma unroll
            for (int k2 = 0; k2 < 4; k2++) {
                const float* c = acc + m * 32 + k2 * 8;
                int b = m * 16 + k2 * 4;
                A3h[b + 0] = lrelu_h2(pack2h(c[0], c[1]), c001);
                A3h[b + 1] = lrelu_h2(pack2h(c[2], c[3]), c001);
                A3h[b + 2] = lrelu_h2(pack2h(c[4], c[5]), c001);
                A3h[b + 3] = lrelu_h2(pack2h(c[6], c[7]), c001);
            }
        }

        // ---- L3: M32 N32 K64, acc init = bias3, single fp16 pass ----
        float acc3[32];
#pragma unroll
        for (int nf = 0; nf < 4; nf++) {
            int n0 = h * 32 + nf * 8 + cq;
            float2 bb = *(const float2*)(b3s + n0);
            acc3[nf * 4 + 0] = bb.x; acc3[nf * 4 + 1] = bb.y;
            acc3[nf * 4 + 2] = bb.x; acc3[nf * 4 + 3] = bb.y;
            acc3[16 + nf * 4 + 0] = bb.x; acc3[16 + nf * 4 + 1] = bb.y;
            acc3[16 + nf * 4 + 2] = bb.x; acc3[16 + nf * 4 + 3] = bb.y;
        }
#pragma unroll
        for (int kf = 0; kf < 4; kf++) {
#pragma unroll
            for (int p = 0; p < 2; p++) {
                uint32_t bh[4];
                ldsm4t(bh, b3com + (kf * 16 * 40 + p * 16) * 2);
#pragma unroll
                for (int m = 0; m < 2; m++) {
                    mmah(acc3 + m * 16 + (2 * p) * 4,     A3h + m * 16 + kf * 4, bh[0], bh[1]);
                    mmah(acc3 + m * 16 + (2 * p + 1) * 4, A3h + m * 16 + kf * 4, bh[2], bh[3]);
                }
            }
        }

        // ---- L4: lrelu + dot(w4) + shfl reduce + store ----
#pragma unroll
        for (int m = 0; m < 2; m++) {
            float sA = 0.f, sB = 0.f;
#pragma unroll
            for (int nf = 0; nf < 4; nf++) {
                int n0 = h * 32 + nf * 8 + cq;
                float w0 = w4s[n0], w1 = w4s[n0 + 1];
                sA += lrelu(acc3[m * 16 + nf * 4 + 0]) * w0 + lrelu(acc3[m * 16 + nf * 4 + 1]) * w1;
                sB += lrelu(acc3[m * 16 + nf * 4 + 2]) * w0 + lrelu(acc3[m * 16 + nf * 4 + 3]) * w1;
            }
            sA += __shfl_xor_sync(0xFFFFFFFFu, sA, 1);
            sA += __shfl_xor_sync(0xFFFFFFFFu, sA, 2);
            sB += __shfl_xor_sync(0xFFFFFFFFu, sB, 1);
            sB += __shfl_xor_sync(0xFFFFFFFFu, sB, 2);
            if ((lane & 3) == 0) {
                int q = lane >> 2;
                out[(size_t)h * NE + e0 + m * 16 + q]     = sA + b4s[h];
                out[(size_t)h * NE + e0 + m * 16 + q + 8] = sB + b4s[h];
            }
        }
        g = gn;
    }
#undef LDE
}

// ------------------------------- launcher ----------------------------------
extern "C" void kernel_launch(void* const* d_in, const int* in_sizes, int n_in,
                              void* d_out, int out_size) {
    const float* x_src = (const float*)d_in[0];
    const float* x_dst = (const float*)d_in[1];
    const void*  eidx  = d_in[2];
    const float* ew1 = (const float*)d_in[3];
    const float* eb1 = (const float*)d_in[4];
    const float* ww1 = (const float*)d_in[5];
    const float* wb1 = (const float*)d_in[6];
    const float* ew2 = (const float*)d_in[7];
    const float* eb2 = (const float*)d_in[8];
    const float* ww2 = (const float*)d_in[9];
    const float* wb2 = (const float*)d_in[10];
    const float* ew3 = (const float*)d_in[11];
    const float* eb3 = (const float*)d_in[12];
    const float* ww3 = (const float*)d_in[13];
    const float* wb3 = (const float*)d_in[14];
    const float* ew4 = (const float*)d_in[15];
    const float* eb4 = (const float*)d_in[16];
    const float* ww4 = (const float*)d_in[17];
    const float* wb4 = (const float*)d_in[18];
    float* out = (float*)d_out;

    cudaFuncSetAttribute(precompute_kernel,
                         cudaFuncAttributeMaxDynamicSharedMemorySize, P_SMEM);
    cudaFuncSetAttribute(main_kernel,
                         cudaFuncAttributeMaxDynamicSharedMemorySize, M_SMEM);

    dim3 pg((NPAD + 255) / 256, 2);
    precompute_kernel<<<pg, 512, P_SMEM>>>(x_src, x_dst, ew1, eb1, ww1, wb1,
                                           (const int*)eidx);
    main_kernel<<<148, THREADS, M_SMEM>>>(
        eidx, ew2, eb2, ww2, wb2, ew3, eb3, ww3, wb3,
        ew4, eb4, ww4, wb4, out);
}

// round 16
// speedup vs baseline: 1.5017x; 1.5017x over previous
#include <cuda_runtime.h>
#include <cuda_bf16.h>
#include <cuda_fp16.h>
#include <cstdint>

// ---------------------------------------------------------------------------
// RegressorHybrid on GB300 via mma.sync (HMMA fallback; tcgen05 not available
// at the harness's compute_103 PTX stage).
//
//   Precompute: P_src[n] = x_src[n] @ W1[0:64]  + bias1   (128 outs: e|w heads)
//               P_dst[n] = x_dst[n] @ W1[64:128]   (3-pass bf16; P stored FP16)
//   Main:       one HEAD per warp, 32 edges (two m16 tiles) per iteration so
//               each weight ldmatrix feeds 4 MMAs. act1 = lrelu(Ps+Pd) in
//               f16x2 via DIRECT inline asm on uint32 registers (no typed
//               __half2 temps / address-of -> no spill-lowering trap).
//               L2/L3 single-pass fp16 mma; 448 threads (146-reg ceiling).
//               L4 scalar dot in fp32.
// ---------------------------------------------------------------------------

#define NE      2000000
#define NNODES  50000
#define NPAD    50048

__device__ __align__(256) __half g_Psrc[(size_t)NPAD * 128];
__device__ __align__(256) __half g_Pdst[(size_t)NPAD * 128];
__device__ int g_flag;   // 1 => edge_label_index is int64

// W2 k-row placement: logical k (0..63) -> physical fragment row, such that
// lane tq's ONE uint4 (8 contiguous fp16 features, logical k = 32b+8tq+j)
// fills its A-fragment slots of kf-groups {2b, 2b+1}.
static __device__ __forceinline__ int kplace(int k) {
    int b = k >> 5, tq = (k >> 3) & 3, j = k & 7;
    int kf = 2 * b + (j >> 2);
    int kp = 2 * tq + (j & 1) + ((j >> 1) & 1) * 8;
    return kf * 16 + kp;
}

// ------------------------------- asm helpers -------------------------------
static __device__ __forceinline__ void ldsm4(uint32_t* r, uint32_t a) {
    asm volatile("ldmatrix.sync.aligned.m8n8.x4.shared.b16 {%0,%1,%2,%3},[%4];"
                 : "=r"(r[0]), "=r"(r[1]), "=r"(r[2]), "=r"(r[3]) : "r"(a));
}
static __device__ __forceinline__ void ldsm4t(uint32_t* r, uint32_t a) {
    asm volatile("ldmatrix.sync.aligned.m8n8.x4.trans.shared.b16 {%0,%1,%2,%3},[%4];"
                 : "=r"(r[0]), "=r"(r[1]), "=r"(r[2]), "=r"(r[3]) : "r"(a));
}
// bf16 mma (precompute kernel)
static __device__ __forceinline__ void mma16816(float* d, const uint32_t* a,
                                                uint32_t b0, uint32_t b1) {
    asm volatile("mma.sync.aligned.m16n8k16.row.col.f32.bf16.bf16.f32 "
                 "{%0,%1,%2,%3},{%4,%5,%6,%7},{%8,%9},{%0,%1,%2,%3};"
                 : "+f"(d[0]), "+f"(d[1]), "+f"(d[2]), "+f"(d[3])
                 : "r"(a[0]), "r"(a[1]), "r"(a[2]), "r"(a[3]), "r"(b0), "r"(b1));
}
// fp16 mma (main kernel)
static __device__ __forceinline__ void mmah(float* d, const uint32_t* a,
                                            uint32_t b0, uint32_t b1) {
    asm volatile("mma.sync.aligned.m16n8k16.row.col.f32.f16.f16.f32 "
                 "{%0,%1,%2,%3},{%4,%5,%6,%7},{%8,%9},{%0,%1,%2,%3};"
                 : "+f"(d[0]), "+f"(d[1]), "+f"(d[2]), "+f"(d[3])
                 : "r"(a[0]), "r"(a[1]), "r"(a[2]), "r"(a[3]), "r"(b0), "r"(b1));
}
// pack two f32 -> bf16x2, x0 in LOW half
static __device__ __forceinline__ uint32_t pack2(float x0, float x1) {
    uint32_t r;
    asm("cvt.rn.bf16x2.f32 %0,%1,%2;" : "=r"(r) : "f"(x1), "f"(x0));
    return r;
}
// pack two f32 -> f16x2, x0 in LOW half
static __device__ __forceinline__ uint32_t pack2h(float x0, float x1) {
    uint32_t r;
    asm("cvt.rn.f16x2.f32 %0,%1,%2;" : "=r"(r) : "f"(x1), "f"(x0));
    return r;
}
static __device__ __forceinline__ float lrelu(float v) {
    return fmaxf(v, 0.01f * v);          // 2 ops: FMUL + FMNMX
}
// f16x2 ops on raw uint32 registers (no typed temps, no address-of)
static __device__ __forceinline__ uint32_t hadd2u(uint32_t a, uint32_t b) {
    uint32_t r;
    asm("add.rn.f16x2 %0,%1,%2;" : "=r"(r) : "r"(a), "r"(b));
    return r;
}
static __device__ __forceinline__ uint32_t lrelu_h2u(uint32_t v, uint32_t c) {
    uint32_t m, r;
    asm("mul.rn.f16x2 %0,%1,%2;" : "=r"(m) : "r"(v), "r"(c));
    asm("max.f16x2 %0,%1,%2;"    : "=r"(r) : "r"(v), "r"(m));
    return r;
}
// bf16 hi/lo split (precompute)
static __device__ __forceinline__ void split_pair(float v0, float v1,
                                                  uint32_t& hw, uint32_t& lw) {
    hw = pack2(v0, v1);
    float h0 = __uint_as_float(hw << 16);
    float h1 = __uint_as_float(hw & 0xFFFF0000u);
    lw = pack2(v0 - h0, v1 - h1);
}
static __device__ __forceinline__ void splitw(float v, __nv_bfloat16& h, __nv_bfloat16& l) {
    h = __float2bfloat16(v);
    l = __float2bfloat16(v - __bfloat162float(h));
}

// ---------------------------- precompute kernel ----------------------------
// blockIdx.y: 0 -> P_src (W1 rows 0..63, +bias), 1 -> P_dst (rows 64..127)
// block (0,0) additionally runs the edge-index dtype detection -> g_flag.
#define P_BW1H 0
#define P_BW1L 17408
#define P_B1   34816
#define P_A    35840
#define P_AW   4608
#define P_SMEM (P_A + 16 * P_AW)      // 109568

__global__ void __launch_bounds__(512, 1) precompute_kernel(
    const float* __restrict__ xs, const float* __restrict__ xd,
    const float* __restrict__ ew1, const float* __restrict__ eb1,
    const float* __restrict__ ww1, const float* __restrict__ wb1,
    const int* __restrict__ eidx_i32)
{
    extern __shared__ char sm[];
    __shared__ int found;
    uint32_t su = (uint32_t)__cvta_generic_to_shared(sm);
    const int tid = threadIdx.x, lane = tid & 31, wid = tid >> 5;
    const int table = blockIdx.y;
    const float* x = table ? xd : xs;
    __half* P = table ? g_Pdst : g_Psrc;

    // ---- edge-index dtype detection (block (0,0) only) ----
    if (blockIdx.x == 0 && table == 0) {
        if (tid == 0) found = 0;
        __syncthreads();
        int acc = 0;
#pragma unroll 4
        for (int i = 0; i < 32; i++) {
            int j = tid * 32 + i;          // j < 16384, safe for both dtypes
            acc |= eidx_i32[2 * j + 1];
        }
        if (acc) atomicOr(&found, 1);
        __syncthreads();
        if (tid == 0) g_flag = found ? 0 : 1;
    }

    // B = W1 rows [table*64, +64), concat e|w heads, K-major [k][n] pad 136
    for (int i = tid; i < 64 * 128; i += 512) {
        int k = i >> 7, n = i & 127;
        int kg = k + table * 64;
        float v = (n < 64) ? ew1[kg * 64 + n] : ww1[kg * 64 + (n - 64)];
        __nv_bfloat16 h, l; splitw(v, h, l);
        *(__nv_bfloat16*)(sm + P_BW1H + (k * 136 + n) * 2) = h;
        *(__nv_bfloat16*)(sm + P_BW1L + (k * 136 + n) * 2) = l;
    }
    if (tid < 128) ((float*)(sm + P_B1))[tid] = (tid < 64) ? eb1[tid] : wb1[tid - 64];
    __syncthreads();

    const int nbase = (blockIdx.x * 16 + wid) * 16;

    // gather 16 node rows into per-warp A tile (16 x 64, pad 72), hi/lo split
    {
        int r = lane >> 1, ch = lane & 1;
        int node = nbase + r; if (node >= NNODES) node = NNODES - 1;
        const float* xr = x + (size_t)node * 64 + ch * 32;
        char* ab = sm + P_A + wid * P_AW + r * 144 + ch * 64;
#pragma unroll
        for (int j = 0; j < 4; j++) {
            float4 a = *(const float4*)(xr + j * 8);
            float4 b = *(const float4*)(xr + j * 8 + 4);
            uint32_t h0, l0, h1, l1, h2, l2, h3, l3;
            split_pair(a.x, a.y, h0, l0); split_pair(a.z, a.w, h1, l1);
            split_pair(b.x, b.y, h2, l2); split_pair(b.z, b.w, h3, l3);
            *(uint4*)(ab + j * 16)        = make_uint4(h0, h1, h2, h3);
            *(uint4*)(ab + 2304 + j * 16) = make_uint4(l0, l1, l2, l3);
        }
    }
    __syncwarp();

    uint32_t Ah[16], Al[16];
    uint32_t aaddr = su + P_A + wid * P_AW + (lane & 15) * 144 + (lane >> 4) * 16;
#pragma unroll
    for (int kf = 0; kf < 4; kf++) {
        ldsm4(Ah + kf * 4, aaddr + kf * 32);
        ldsm4(Al + kf * 4, aaddr + 2304 + kf * 32);
    }

    float acc[64];
#pragma unroll
    for (int i = 0; i < 64; i++) acc[i] = 0.f;

    uint32_t bcom = su + ((lane & 15) * 136 + (lane >> 4) * 8) * 2;
#pragma unroll
    for (int kf = 0; kf < 4; kf++) {
#pragma unroll
        for (int p = 0; p < 8; p++) {
            uint32_t bh[4]; ldsm4t(bh, bcom + P_BW1H + (kf * 16 * 136 + p * 16) * 2);
            mma16816(acc + (2 * p) * 4,     Ah + kf * 4, bh[0], bh[1]);
            mma16816(acc + (2 * p + 1) * 4, Ah + kf * 4, bh[2], bh[3]);
            mma16816(acc + (2 * p) * 4,     Al + kf * 4, bh[0], bh[1]);
            mma16816(acc + (2 * p + 1) * 4, Al + kf * 4, bh[2], bh[3]);
            uint32_t bl[4]; ldsm4t(bl, bcom + P_BW1L + (kf * 16 * 136 + p * 16) * 2);
            mma16816(acc + (2 * p) * 4,     Ah + kf * 4, bl[0], bl[1]);
            mma16816(acc + (2 * p + 1) * 4, Ah + kf * 4, bl[2], bl[3]);
        }
    }

    const float* b1s = (const float*)(sm + P_B1);
    int r0 = nbase + (lane >> 2), r1 = r0 + 8;
#pragma unroll
    for (int nf = 0; nf < 16; nf++) {
        int n0 = nf * 8 + (lane & 3) * 2;
        float a0 = 0.f, a1 = 0.f;
        if (table == 0) { a0 = b1s[n0]; a1 = b1s[n0 + 1]; }
        if (r0 < NNODES)
            *(uint32_t*)(P + (size_t)r0 * 128 + n0) = pack2h(acc[nf * 4 + 0] + a0, acc[nf * 4 + 1] + a1);
        if (r1 < NNODES)
            *(uint32_t*)(P + (size_t)r1 * 128 + n0) = pack2h(acc[nf * 4 + 2] + a0, acc[nf * 4 + 3] + a1);
    }
}

// ------------------------------- main kernel -------------------------------
// fp16 weight tables: W2 [h][64][72] (kplace'd rows), W3 [h][64][40]
#define M_W2  0
#define M_W3  18432
#define M_B2  28672
#define M_B3  29184
#define M_W4  29440
#define M_B4  29696
#define M_SMEM 30720

#define THREADS 448
#define HWARPS  7    // warps per head per CTA (14 warps total)

__global__ void __launch_bounds__(THREADS, 1) main_kernel(
    const void* __restrict__ eidx_raw,
    const float* __restrict__ ew2, const float* __restrict__ eb2,
    const float* __restrict__ ww2, const float* __restrict__ wb2,
    const float* __restrict__ ew3, const float* __restrict__ eb3,
    const float* __restrict__ ww3, const float* __restrict__ wb3,
    const float* __restrict__ ew4, const float* __restrict__ eb4,
    const float* __restrict__ ww4, const float* __restrict__ wb4,
    float* __restrict__ out)
{
    extern __shared__ char sm[];
    uint32_t su = (uint32_t)__cvta_generic_to_shared(sm);
    const int tid = threadIdx.x, lane = tid & 31, wid = tid >> 5;

    // weights (fp16): W2 rows at kplace(k) (gather-matched), W3 identity
    for (int i = tid; i < 2 * 64 * 64; i += THREADS) {
        int h = i >> 12, r = i & 4095, k = r >> 6, n = r & 63;
        float v = h ? ww2[k * 64 + n] : ew2[k * 64 + n];
        *(__half*)(sm + M_W2 + (h * 64 * 72 + kplace(k) * 72 + n) * 2) = __float2half(v);
    }
    for (int i = tid; i < 2 * 64 * 32; i += THREADS) {
        int h = i >> 11, r = i & 2047, k = r >> 5, n = r & 31;
        float v = h ? ww3[k * 32 + n] : ew3[k * 32 + n];
        *(__half*)(sm + M_W3 + (h * 64 * 40 + k * 40 + n) * 2) = __float2half(v);
    }
    if (tid < 128) ((float*)(sm + M_B2))[tid] = (tid < 64) ? eb2[tid] : wb2[tid - 64];
    else if (tid < 192) { int c = tid - 128; ((float*)(sm + M_B3))[c] = (c < 32) ? eb3[c] : wb3[c - 32]; }
    else if (tid < 256) { int c = tid - 192; ((float*)(sm + M_W4))[c] = (c < 32) ? ew4[c] : ww4[c - 32]; }
    if (tid == 256) { ((float*)(sm + M_B4))[0] = eb4[0]; ((float*)(sm + M_B4))[1] = wb4[0]; }
    __syncthreads();

    const int idx64 = g_flag;
    const long long* e64 = (const long long*)eidx_raw;
    const int* e32 = (const int*)eidx_raw;
    const float* b2s = (const float*)(sm + M_B2);
    const float* b3s = (const float*)(sm + M_B3);
    const float* w4s = (const float*)(sm + M_W4);
    const float* b4s = (const float*)(sm + M_B4);

    const uint32_t c001 = pack2h(0.01f, 0.01f);  // f16x2 constant 0.01

    const int h = wid & 1;                       // this warp's head
    const int hw = wid >> 1;                     // warp index within head: 0..6
    const uint32_t b2com = su + M_W2 + ((lane & 15) * 72 + (lane >> 4) * 8) * 2 + h * 9216;
    const uint32_t b3com = su + M_W3 + ((lane & 15) * 40 + (lane >> 4) * 8) * 2 + h * 5120;

    const int ngroups = NE / 32;                 // 62500 groups of 32 edges
    const int gstride = gridDim.x * HWARPS;
    const int rq = lane >> 2;                    // row 0..7 within m8
    const int cq = (lane & 3) * 2;               // col pair base within 8 (N dims)
    const int tq8 = (lane & 3) * 8;              // 8-feature base within 32-block

#define LDE(i) (idx64 ? (int)__ldg(e64 + (i)) : __ldg(e32 + (i)))

    int g = blockIdx.x * HWARPS + hw;
    int s0 = 0, s1 = 0, s2 = 0, s3 = 0, d0 = 0, d1 = 0, d2 = 0, d3 = 0;
    if (g < ngroups) {
        int r0 = g * 32 + rq;
        s0 = LDE(r0);      s1 = LDE(r0 + 8);      s2 = LDE(r0 + 16);      s3 = LDE(r0 + 24);
        d0 = LDE(NE + r0); d1 = LDE(NE + r0 + 8); d2 = LDE(NE + r0 + 16); d3 = LDE(NE + r0 + 24);
    }

    const size_t hco = (size_t)(h * 64 + tq8);

    for (; g < ngroups; ) {
        const int e0 = g * 32;
        const __half* ps0 = g_Psrc + (size_t)s0 * 128 + hco;
        const __half* pd0 = g_Pdst + (size_t)d0 * 128 + hco;
        const __half* ps1 = g_Psrc + (size_t)s1 * 128 + hco;
        const __half* pd1 = g_Pdst + (size_t)d1 * 128 + hco;
        const __half* ps2 = g_Psrc + (size_t)s2 * 128 + hco;
        const __half* pd2 = g_Pdst + (size_t)d2 * 128 + hco;
        const __half* ps3 = g_Psrc + (size_t)s3 * 128 + hco;
        const __half* pd3 = g_Pdst + (size_t)d3 * 128 + hco;

        // prefetch next iteration's indices (hides one L2 latency level)
        const int gn = g + gstride;
        if (gn < ngroups) {
            int r0 = gn * 32 + rq;
            s0 = LDE(r0);      s1 = LDE(r0 + 8);      s2 = LDE(r0 + 16);      s3 = LDE(r0 + 24);
            d0 = LDE(NE + r0); d1 = LDE(NE + r0 + 8); d2 = LDE(NE + r0 + 16); d3 = LDE(NE + r0 + 24);
        }

        // ---- gather act1 into fp16 A frags: 16 LDG.128, raw f16x2 asm ----
        uint32_t Ah[32];
#define GATH(sa, da, idx) Ah[idx] = lrelu_h2u(hadd2u((sa), (da)), c001)
#pragma unroll
        for (int b = 0; b < 2; b++) {
            int co = b * 32;
            uint4 us0 = __ldg((const uint4*)(ps0 + co));
            uint4 ud0 = __ldg((const uint4*)(pd0 + co));
            uint4 us1 = __ldg((const uint4*)(ps1 + co));
            uint4 ud1 = __ldg((const uint4*)(pd1 + co));
            uint4 us2 = __ldg((const uint4*)(ps2 + co));
            uint4 ud2 = __ldg((const uint4*)(pd2 + co));
            uint4 us3 = __ldg((const uint4*)(ps3 + co));
            uint4 ud3 = __ldg((const uint4*)(pd3 + co));
            GATH(us0.x, ud0.x, 8 * b + 0);
            GATH(us0.y, ud0.y, 8 * b + 2);
            GATH(us0.z, ud0.z, 8 * b + 4);
            GATH(us0.w, ud0.w, 8 * b + 6);
            GATH(us1.x, ud1.x, 8 * b + 1);
            GATH(us1.y, ud1.y, 8 * b + 3);
            GATH(us1.z, ud1.z, 8 * b + 5);
            GATH(us1.w, ud1.w, 8 * b + 7);
            GATH(us2.x, ud2.x, 16 + 8 * b + 0);
            GATH(us2.y, ud2.y, 16 + 8 * b + 2);
            GATH(us2.z, ud2.z, 16 + 8 * b + 4);
            GATH(us2.w, ud2.w, 16 + 8 * b + 6);
            GATH(us3.x, ud3.x, 16 + 8 * b + 1);
            GATH(us3.y, ud3.y, 16 + 8 * b + 3);
            GATH(us3.z, ud3.z, 16 + 8 * b + 5);
            GATH(us3.w, ud3.w, 16 + 8 * b + 7);
        }
#undef GATH

        // ---- L2: M32 N64 K64, acc init = bias2, single fp16 pass ----
        float acc[64];
#pragma unroll
        for (int nf = 0; nf < 8; nf++) {
            int n0 = h * 64 + nf * 8 + cq;
            float2 bb = *(const float2*)(b2s + n0);
            acc[nf * 4 + 0] = bb.x; acc[nf * 4 + 1] = bb.y;
            acc[nf * 4 + 2] = bb.x; acc[nf * 4 + 3] = bb.y;
            acc[32 + nf * 4 + 0] = bb.x; acc[32 + nf * 4 + 1] = bb.y;
            acc[32 + nf * 4 + 2] = bb.x; acc[32 + nf * 4 + 3] = bb.y;
        }
#pragma unroll
        for (int kf = 0; kf < 4; kf++) {
#pragma unroll
            for (int p = 0; p < 4; p++) {
                uint32_t bh[4];
                ldsm4t(bh, b2com + (kf * 16 * 72 + p * 16) * 2);
#pragma unroll
                for (int m = 0; m < 2; m++) {
                    mmah(acc + m * 32 + (2 * p) * 4,     Ah + m * 16 + kf * 4, bh[0], bh[1]);
                    mmah(acc + m * 32 + (2 * p + 1) * 4, Ah + m * 16 + kf * 4, bh[2], bh[3]);
                }
            }
        }

        // ---- epilogue2: pack fp16 then f16x2 lrelu -> A3 frags (regs) ----
        uint32_t A3h[32];
#pragma unroll
        for (int m = 0; m < 2; m++) {
#pragma unroll
            for (int k2 = 0; k2 < 4; k2++) {
                const float* c = acc + m * 32 + k2 * 8;
                int b = m * 16 + k2 * 4;
                A3h[b + 0] = lrelu_h2u(pack2h(c[0], c[1]), c001);
                A3h[b + 1] = lrelu_h2u(pack2h(c[2], c[3]), c001);
                A3h[b + 2] = lrelu_h2u(pack2h(c[4], c[5]), c001);
                A3h[b + 3] = lrelu_h2u(pack2h(c[6], c[7]), c001);
            }
        }

        // ---- L3: M32 N32 K64, acc init = bias3, single fp16 pass ----
        float acc3[32];
#pragma unroll
        for (int nf = 0; nf < 4; nf++) {
            int n0 = h * 32 + nf * 8 + cq;
            float2 bb = *(const float2*)(b3s + n0);
            acc3[nf * 4 + 0] = bb.x; acc3[nf * 4 + 1] = bb.y;
            acc3[nf * 4 + 2] = bb.x; acc3[nf * 4 + 3] = bb.y;
            acc3[16 + nf * 4 + 0] = bb.x; acc3[16 + nf * 4 + 1] = bb.y;
            acc3[16 + nf * 4 + 2] = bb.x; acc3[16 + nf * 4 + 3] = bb.y;
        }
#pragma unroll
        for (int kf = 0; kf < 4; kf++) {
#pragma unroll
            for (int p = 0; p < 2; p++) {
                uint32_t bh[4];
                ldsm4t(bh, b3com + (kf * 16 * 40 + p * 16) * 2);
#pragma unroll
                for (int m = 0; m < 2; m++) {
                    mmah(acc3 + m * 16 + (2 * p) * 4,     A3h + m * 16 + kf * 4, bh[0], bh[1]);
                    mmah(acc3 + m * 16 + (2 * p + 1) * 4, A3h + m * 16 + kf * 4, bh[2], bh[3]);
                }
            }
        }

        // ---- L4: lrelu + dot(w4) + shfl reduce + store ----
#pragma unroll
        for (int m = 0; m < 2; m++) {
            float sA = 0.f, sB = 0.f;
#pragma unroll
            for (int nf = 0; nf < 4; nf++) {
                int n0 = h * 32 + nf * 8 + cq;
                float w0 = w4s[n0], w1 = w4s[n0 + 1];
                sA += lrelu(acc3[m * 16 + nf * 4 + 0]) * w0 + lrelu(acc3[m * 16 + nf * 4 + 1]) * w1;
                sB += lrelu(acc3[m * 16 + nf * 4 + 2]) * w0 + lrelu(acc3[m * 16 + nf * 4 + 3]) * w1;
            }
            sA += __shfl_xor_sync(0xFFFFFFFFu, sA, 1);
            sA += __shfl_xor_sync(0xFFFFFFFFu, sA, 2);
            sB += __shfl_xor_sync(0xFFFFFFFFu, sB, 1);
            sB += __shfl_xor_sync(0xFFFFFFFFu, sB, 2);
            if ((lane & 3) == 0) {
                int q = lane >> 2;
                out[(size_t)h * NE + e0 + m * 16 + q]     = sA + b4s[h];
                out[(size_t)h * NE + e0 + m * 16 + q + 8] = sB + b4s[h];
            }
        }
        g = gn;
    }
#undef LDE
}

// ------------------------------- launcher ----------------------------------
extern "C" void kernel_launch(void* const* d_in, const int* in_sizes, int n_in,
                              void* d_out, int out_size) {
    const float* x_src = (const float*)d_in[0];
    const float* x_dst = (const float*)d_in[1];
    const void*  eidx  = d_in[2];
    const float* ew1 = (const float*)d_in[3];
    const float* eb1 = (const float*)d_in[4];
    const float* ww1 = (const float*)d_in[5];
    const float* wb1 = (const float*)d_in[6];
    const float* ew2 = (const float*)d_in[7];
    const float* eb2 = (const float*)d_in[8];
    const float* ww2 = (const float*)d_in[9];
    const float* wb2 = (const float*)d_in[10];
    const float* ew3 = (const float*)d_in[11];
    const float* eb3 = (const float*)d_in[12];
    const float* ww3 = (const float*)d_in[13];
    const float* wb3 = (const float*)d_in[14];
    const float* ew4 = (const float*)d_in[15];
    const float* eb4 = (const float*)d_in[16];
    const float* ww4 = (const float*)d_in[17];
    const float* wb4 = (const float*)d_in[18];
    float* out = (float*)d_out;

    cudaFuncSetAttribute(precompute_kernel,
                         cudaFuncAttributeMaxDynamicSharedMemorySize, P_SMEM);
    cudaFuncSetAttribute(main_kernel,
                         cudaFuncAttributeMaxDynamicSharedMemorySize, M_SMEM);

    dim3 pg((NPAD + 255) / 256, 2);
    precompute_kernel<<<pg, 512, P_SMEM>>>(x_src, x_dst, ew1, eb1, ww1, wb1,
                                           (const int*)eidx);
    main_kernel<<<148, THREADS, M_SMEM>>>(
        eidx, ew2, eb2, ww2, wb2, ew3, eb3, ww3, wb3,
        ew4, eb4, ww4, wb4, out);
}